// round 7
// baseline (speedup 1.0000x reference)
#include <cuda_runtime.h>
#include <cuda_fp16.h>
#include <math.h>
#include <stdint.h>

// Fixed problem shape: B=16 channels, T=2^20 samples, 48 kHz.
constexpr int T_LEN   = 1 << 20;
constexpr int BCH     = 16;
constexpr int CHUNK   = 2048;               // samples produced per serial worker
constexpr int WARM_CH = 8;                  // warm-up chunks (16384 samples)
constexpr int PER_CH  = T_LEN / CHUNK;      // 512 chunks per channel
constexpr int NWORK   = BCH * PER_CH;       // 8192 serial workers (256 warps)
constexpr int ROWS    = CHUNK / 4;          // 512 float4 rows per chunk column
constexpr int GPC     = CHUNK / 8;          // 256 8-sample groups per chunk

// Transposed scratch arrays, [row][worker] with row stride NWORK.
// (A,R) = (aatt*gr, arel*gr) packed half2, 4 samples per float4 row. (~66 MB)
__device__ uint4  d_grT [(size_t)(ROWS + 16) * NWORK];
// Composed-map intercepts per 8-sample group: classes 1..8 in two float4 rows. (~68 MB)
__device__ float4 d_c14T[(size_t)(2 * GPC + 32) * NWORK];
// Class-0 intercept per group. (~9 MB)
__device__ float  d_c0T [(size_t)(GPC + 16) * NWORK];
// Smoothed envelope g, [row][worker] float4 (4 samples). (64 MB)
__device__ float4 d_gt  [(size_t)ROWS * NWORK];

__device__ __forceinline__ float f_lg2(float x) {
    float r; asm("lg2.approx.f32 %0, %1;" : "=f"(r) : "f"(x)); return r;
}
__device__ __forceinline__ float f_ex2(float x) {
    float r; asm("ex2.approx.ftz.f32 %0, %1;" : "=f"(r) : "f"(x)); return r;
}

// ---------------------------------------------------------------------------
// Pass 1: gain computer + per-group max-plus composition DP + transpose.
//   gr = max( (20*log10(|a|+1e-8) - thr) * (1 - 1/ratio), 0 )
// One step is g' = max(ba*g + A, br*g + R); composing 8 steps collapses the
// 2^8 paths into 9 slope classes s_m = ba^m * br^(8-m) with per-class max
// intercepts c_m, computed here by a small DP and stored per group.
// ---------------------------------------------------------------------------
__global__ void __launch_bounds__(256)
pg_kernel(const float* __restrict__ audio,
          const float* __restrict__ p_thr,
          const float* __restrict__ p_ratio,
          const float* __restrict__ p_att,
          const float* __restrict__ p_rel)
{
    __shared__ float4 tile[8][33];
    const int tid = threadIdx.x;
    const int r0  = blockIdx.x * 8;       // gr-row tile origin (8 rows = 32 samples)
    const int w0  = blockIdx.y * 32;      // worker tile origin

    const float R    = 1.0f - 1.0f / (*p_ratio);
    const float kl   = 6.0205999132796239f * R;   // 20*log10(2) * R
    const float kc   = -(*p_thr) * R;
    const float ba   = expf(-1.0f / ((*p_att) * 48000.0f));  // 1 - alpha_attack
    const float br   = expf(-1.0f / ((*p_rel) * 48000.0f));  // 1 - alpha_release
    const float aatt = 1.0f - ba;
    const float arel = 1.0f - br;

    // Phase A: coalesced audio reads -> gr into smem tile.
    {
        const int wl   = tid >> 3;        // 0..31 worker within tile
        const int rowk = tid & 7;         // 0..7  gr-row within tile
        const int w = w0 + wl;
        const int b = w >> 9;             // channel  (PER_CH = 512)
        const int j = w & 511;            // chunk within channel
        const size_t aidx = (size_t)b * T_LEN + (size_t)j * CHUNK
                          + (size_t)(r0 + rowk) * 4;
        float4 a = *reinterpret_cast<const float4*>(audio + aidx);
        float4 gr;
        gr.x = fmaxf(fmaf(kl, f_lg2(fabsf(a.x) + 1e-8f), kc), 0.0f);
        gr.y = fmaxf(fmaf(kl, f_lg2(fabsf(a.y) + 1e-8f), kc), 0.0f);
        gr.z = fmaxf(fmaf(kl, f_lg2(fabsf(a.z) + 1e-8f), kc), 0.0f);
        gr.w = fmaxf(fmaf(kl, f_lg2(fabsf(a.w) + 1e-8f), kc), 0.0f);
        tile[rowk][wl] = gr;
    }
    __syncthreads();

    // Phase B1: transposed half2(A,R) writes (all 256 threads).
    {
        const int rowk = tid >> 5;        // 0..7
        const int wl   = tid & 31;        // 0..31
        float4 grv = tile[rowk][wl];
        uint4 o;
        o.x = __half2_raw(__floats2half2_rn(aatt * grv.x, arel * grv.x)).x;
        o.y = __half2_raw(__floats2half2_rn(aatt * grv.y, arel * grv.y)).x;
        o.z = __half2_raw(__floats2half2_rn(aatt * grv.z, arel * grv.z)).x;
        o.w = __half2_raw(__floats2half2_rn(aatt * grv.w, arel * grv.w)).x;
        d_grT[(size_t)(r0 + rowk) * NWORK + (w0 + wl)] = o;
    }

    // Phase B2: max-plus DP over each 8-sample group (128 threads: 4 groups x 32 workers).
    if (tid < 128) {
        const int wl  = tid & 31;
        const int grp = tid >> 5;         // 0..3 group within tile
        const int g0  = blockIdx.x * 4 + grp;   // global group row
        float4 u = tile[grp * 2][wl];
        float4 v = tile[grp * 2 + 1][wl];
        float gr8[8] = {u.x, u.y, u.z, u.w, v.x, v.y, v.z, v.w};

        float c[9];
        c[0] = arel * gr8[0];             // all-release path
        c[1] = aatt * gr8[0];             // one-attack path
#pragma unroll
        for (int t = 1; t < 8; ++t) {
            const float A  = aatt * gr8[t];
            const float Rr = arel * gr8[t];
            c[t + 1] = fmaf(ba, c[t], A);           // promote from old c[t]
#pragma unroll
            for (int m = 7; m >= 1; --m) {          // downward: c[m-1] still old
                if (m <= t)
                    c[m] = fmaxf(fmaf(ba, c[m - 1], A), fmaf(br, c[m], Rr));
            }
            c[0] = fmaf(br, c[0], Rr);
        }
        const size_t base = (size_t)g0 * 2 * NWORK + (w0 + wl);
        d_c14T[base]         = make_float4(c[1], c[2], c[3], c[4]);
        d_c14T[base + NWORK] = make_float4(c[5], c[6], c[7], c[8]);
        d_c0T[(size_t)g0 * NWORK + (w0 + wl)] = c[0];
    }
}

// ---------------------------------------------------------------------------
// Pass 2: chunked serial envelope scan over composed 8-step maps.
// ---------------------------------------------------------------------------
struct Slopes { float s[9]; };

__device__ __forceinline__ float fwd(float g, const Slopes& S,
                                     float4 ca, float4 cb, float c0)
{
    float f0 = fmaf(S.s[0], g, c0);
    float f1 = fmaf(S.s[1], g, ca.x);
    float f2 = fmaf(S.s[2], g, ca.y);
    float f3 = fmaf(S.s[3], g, ca.z);
    float f4 = fmaf(S.s[4], g, ca.w);
    float f5 = fmaf(S.s[5], g, cb.x);
    float f6 = fmaf(S.s[6], g, cb.y);
    float f7 = fmaf(S.s[7], g, cb.z);
    float f8 = fmaf(S.s[8], g, cb.w);
    float a = fmaxf(f0, f1), b = fmaxf(f2, f3);
    float c = fmaxf(f4, f5), d = fmaxf(f6, f7);
    float e = fmaxf(a, b),   h = fmaxf(c, d);
    return fmaxf(fmaxf(e, h), f8);
}

// Warm-up over one chunk column c (no stores). If `pre`, prefetch the gr rows
// of column w (consumed next, in the store phase) into L2.
__device__ __forceinline__ void warm_col(int c, int w, float& g,
                                         const Slopes& S, bool pre)
{
    const float4* C14 = d_c14T + c;
    const float*  C0  = d_c0T + c;
    float4 A[8], B[8]; float Z[8];
#pragma unroll
    for (int n = 0; n < 6; ++n) {
        A[n] = C14[(size_t)(2 * n) * NWORK];
        B[n] = C14[(size_t)(2 * n + 1) * NWORK];
        Z[n] = C0[(size_t)n * NWORK];
    }
#pragma unroll 1
    for (int it = 0; it < GPC; it += 8) {
#pragma unroll
        for (int u = 0; u < 8; ++u) {
            const int gl = it + u + 6;            // stage to load (pad rows absorb tail)
            A[(u + 6) & 7] = C14[(size_t)(2 * gl) * NWORK];
            B[(u + 6) & 7] = C14[(size_t)(2 * gl + 1) * NWORK];
            Z[(u + 6) & 7] = C0[(size_t)gl * NWORK];
            if (pre && (u & 1) == 0) {
                // two 128B rows per two groups: full coverage, half the issue cost
                const uint4* pf = d_grT + (size_t)(2 * (it + u)) * NWORK + w;
                asm volatile("prefetch.global.L2 [%0];" :: "l"(pf));
                asm volatile("prefetch.global.L2 [%0];" :: "l"(pf + 2 * (size_t)NWORK));
            }
            g = fwd(g, S, A[u & 7], B[u & 7], Z[u & 7]);
        }
    }
}

// Store phase over column w: composed forward chain + off-chain per-sample
// reconstruction from half2 (A,R), envelope stored transposed.
__device__ __forceinline__ void store_col(int w, float& g, const Slopes& S,
                                          float ba, float br)
{
    const float4* C14 = d_c14T + w;
    const float*  C0  = d_c0T + w;
    const uint4*  GR  = d_grT + w;
    float4* GT = d_gt + w;

    float4 A[4], B[4]; float Z[4]; uint4 Ga[4], Gb[4];
#pragma unroll
    for (int n = 0; n < 3; ++n) {
        A[n]  = C14[(size_t)(2 * n) * NWORK];
        B[n]  = C14[(size_t)(2 * n + 1) * NWORK];
        Z[n]  = C0[(size_t)n * NWORK];
        Ga[n] = __ldcs(&GR[(size_t)(2 * n) * NWORK]);
        Gb[n] = __ldcs(&GR[(size_t)(2 * n + 1) * NWORK]);
    }
#pragma unroll 1
    for (int it = 0; it < GPC; it += 4) {
#pragma unroll
        for (int u = 0; u < 4; ++u) {
            const int gl = it + u + 3;
            A[(u + 3) & 3]  = C14[(size_t)(2 * gl) * NWORK];
            B[(u + 3) & 3]  = C14[(size_t)(2 * gl + 1) * NWORK];
            Z[(u + 3) & 3]  = C0[(size_t)gl * NWORK];
            Ga[(u + 3) & 3] = __ldcs(&GR[(size_t)(2 * gl) * NWORK]);
            Gb[(u + 3) & 3] = __ldcs(&GR[(size_t)(2 * gl + 1) * NWORK]);

            const float gp = g;                           // state before group
            g = fwd(g, S, A[u & 3], B[u & 3], Z[u & 3]);  // critical chain

            // Off-chain reconstruction of the 8 intra-group envelope values.
            const int gi = it + u;
            float h = gp;
            {
                uint4 q = Ga[u & 3]; float4 o;
                float2 p;
                p = __half22float2(*reinterpret_cast<__half2*>(&q.x));
                h = fmaxf(fmaf(ba, h, p.x), fmaf(br, h, p.y)); o.x = h;
                p = __half22float2(*reinterpret_cast<__half2*>(&q.y));
                h = fmaxf(fmaf(ba, h, p.x), fmaf(br, h, p.y)); o.y = h;
                p = __half22float2(*reinterpret_cast<__half2*>(&q.z));
                h = fmaxf(fmaf(ba, h, p.x), fmaf(br, h, p.y)); o.z = h;
                p = __half22float2(*reinterpret_cast<__half2*>(&q.w));
                h = fmaxf(fmaf(ba, h, p.x), fmaf(br, h, p.y)); o.w = h;
                __stcs(&GT[(size_t)(2 * gi) * NWORK], o);
            }
            {
                uint4 q = Gb[u & 3]; float4 o;
                float2 p;
                p = __half22float2(*reinterpret_cast<__half2*>(&q.x));
                h = fmaxf(fmaf(ba, h, p.x), fmaf(br, h, p.y)); o.x = h;
                p = __half22float2(*reinterpret_cast<__half2*>(&q.y));
                h = fmaxf(fmaf(ba, h, p.x), fmaf(br, h, p.y)); o.y = h;
                p = __half22float2(*reinterpret_cast<__half2*>(&q.z));
                h = fmaxf(fmaf(ba, h, p.x), fmaf(br, h, p.y)); o.z = h;
                p = __half22float2(*reinterpret_cast<__half2*>(&q.w));
                h = fmaxf(fmaf(ba, h, p.x), fmaf(br, h, p.y)); o.w = h;
                __stcs(&GT[(size_t)(2 * gi + 1) * NWORK], o);
            }
        }
    }
}

__global__ void __launch_bounds__(32)
scan_kernel(const float* __restrict__ p_att,
            const float* __restrict__ p_rel)
{
    const int w = blockIdx.x * 32 + threadIdx.x;
    const int j = w & 511;                      // chunk within channel

    const float ba = expf(-1.0f / ((*p_att) * 48000.0f));
    const float br = expf(-1.0f / ((*p_rel) * 48000.0f));
    Slopes S;
    {
        float p = 1.0f;
#pragma unroll
        for (int m = 0; m <= 8; ++m) { S.s[m] = p; p *= ba; }   // ba^m
        float q = 1.0f;
#pragma unroll
        for (int m = 8; m >= 0; --m) { S.s[m] *= q; q *= br; }  // * br^(8-m)
    }

    float g = 0.0f;
    // Warm-up over the 8 preceding chunk columns. Lanes whose warm-up spans
    // their channel start get reset to the exact initial state g=0 at the
    // phase where the channel-start column is processed.
#pragma unroll 1
    for (int i = 0; i < WARM_CH; ++i) {
        if (WARM_CH - j == i) g = 0.0f;
        int c = w - WARM_CH + i;
        if (c < 0) c = 0;
        warm_col(c, w, g, S, i == WARM_CH - 1);
    }
    if (j == 0) g = 0.0f;
    store_col(w, g, S, ba, br);
}

// ---------------------------------------------------------------------------
// Pass 3: tiled un-transpose of the envelope + output gain.
//   out = audio * 2^( -K*g + K*makeup ),  K = log2(10)/20
// ---------------------------------------------------------------------------
__global__ void __launch_bounds__(256)
out_kernel(const float* __restrict__ audio,
           const float* __restrict__ p_mk,
           float* __restrict__ out)
{
    __shared__ float tile[32][33];
    const int tx  = threadIdx.x;           // 0..31
    const int ty  = threadIdx.y;           // 0..7
    const int sb0 = blockIdx.x * 8;        // 8 float4 rows = 32 samples
    const int s0  = blockIdx.x * 32;
    const int w0  = blockIdx.y * 32;

    float4 v = __ldcs(&d_gt[(size_t)(sb0 + ty) * NWORK + (w0 + tx)]);
    tile[ty * 4 + 0][tx] = v.x;
    tile[ty * 4 + 1][tx] = v.y;
    tile[ty * 4 + 2][tx] = v.z;
    tile[ty * 4 + 3][tx] = v.w;
    __syncthreads();

    const float K  = 0.16609640474436813f;  // log2(10)/20
    const float c3 = -K;
    const float c4 = (*p_mk) * K;

#pragma unroll
    for (int r = 0; r < 4; ++r) {
        const int wl = r * 8 + ty;
        const int w  = w0 + wl;
        const int b  = w >> 9;
        const int j  = w & 511;
        const size_t idx = (size_t)b * T_LEN + (size_t)j * CHUNK + s0 + tx;
        out[idx] = audio[idx] * f_ex2(fmaf(c3, tile[tx][wl], c4));
    }
}

// Fallback for unexpected shapes (never taken for this dataset).
__global__ void fallback_kernel(const float* __restrict__ audio,
                                const float* __restrict__ p_thr,
                                const float* __restrict__ p_ratio,
                                const float* __restrict__ p_att,
                                const float* __restrict__ p_rel,
                                const float* __restrict__ p_mk,
                                float* __restrict__ out, int Bn, int Tn)
{
    int c = blockIdx.x * blockDim.x + threadIdx.x;
    if (c >= Bn) return;
    const float R  = 1.0f - 1.0f / (*p_ratio);
    const float aa = 1.0f - expf(-1.0f / ((*p_att) * 48000.0f));
    const float ar = 1.0f - expf(-1.0f / ((*p_rel) * 48000.0f));
    const float K  = 0.16609640474436813f;
    float g = 0.0f;
    for (int t = 0; t < Tn; ++t) {
        float a  = audio[(size_t)c * Tn + t];
        float gr = fmaxf((20.0f * log10f(fabsf(a) + 1e-8f) - *p_thr) * R, 0.0f);
        if (t > 0) { float al = gr > g ? aa : ar; g = (1.0f - al) * g + al * gr; }
        out[(size_t)c * Tn + t] = a * f_ex2(fmaf(-K, g, (*p_mk) * K));
    }
}

extern "C" void kernel_launch(void* const* d_in, const int* in_sizes, int n_in,
                              void* d_out, int out_size)
{
    const float* audio   = (const float*)d_in[0];
    const float* thr     = (const float*)d_in[1];
    const float* ratio   = (const float*)d_in[2];
    const float* attack  = (const float*)d_in[3];
    const float* release = (const float*)d_in[4];
    const float* makeup  = (const float*)d_in[5];
    float* out = (float*)d_out;

    const int n = in_sizes[0];
    if (n == BCH * T_LEN) {
        pg_kernel<<<dim3(ROWS / 8, NWORK / 32), 256>>>(audio, thr, ratio,
                                                       attack, release);
        scan_kernel<<<NWORK / 32, 32>>>(attack, release);
        out_kernel<<<dim3(ROWS / 8, NWORK / 32), dim3(32, 8)>>>(audio, makeup, out);
    } else {
        fallback_kernel<<<1, 32>>>(audio, thr, ratio, attack, release, makeup,
                                   out, BCH, n / BCH);
    }
}